// round 11
// baseline (speedup 1.0000x reference)
#include <cuda_runtime.h>
#include <cuda_fp16.h>
#include <math.h>
#include <cstdint>

#define NB 32
#define NN 512

// Scratch (device globals; allocation-free per harness rules).
__device__ __align__(16) __half g_c16[(size_t)NB * NN * NN];   // fp16 c [m][k]
__device__ __align__(16) __half g_a16a[(size_t)NB * NN * NN];  // fp16 a ping
__device__ __align__(16) __half g_a16b[(size_t)NB * NN * NN];  // fp16 a pong

// ---------------------------------------------------------------------------
__device__ __forceinline__ uint32_t smem_u32(const void* p) {
    uint32_t a;
    asm("{ .reg .u64 t; cvta.to.shared.u64 t, %1; cvt.u32.u64 %0, t; }" : "=r"(a) : "l"(p));
    return a;
}
__device__ __forceinline__ void cp_async16(uint32_t saddr, const void* gaddr) {
    asm volatile("cp.async.cg.shared.global [%0], [%1], 16;" :: "r"(saddr), "l"(gaddr) : "memory");
}
__device__ __forceinline__ void cp_commit() { asm volatile("cp.async.commit_group;" ::: "memory"); }
__device__ __forceinline__ void cp_wait0()  { asm volatile("cp.async.wait_group 0;" ::: "memory"); }
__device__ __forceinline__ void ldsm_x4(uint32_t* r, uint32_t addr) {
    asm volatile("ldmatrix.sync.aligned.m8n8.x4.shared.b16 {%0,%1,%2,%3}, [%4];"
                 : "=r"(r[0]), "=r"(r[1]), "=r"(r[2]), "=r"(r[3]) : "r"(addr));
}
__device__ __forceinline__ void ldsm_x4_t(uint32_t* r, uint32_t addr) {
    asm volatile("ldmatrix.sync.aligned.m8n8.x4.trans.shared.b16 {%0,%1,%2,%3}, [%4];"
                 : "=r"(r[0]), "=r"(r[1]), "=r"(r[2]), "=r"(r[3]) : "r"(addr));
}
__device__ __forceinline__ void mma_fp16(float* d, const uint32_t* a, const uint32_t* b) {
    asm volatile(
        "mma.sync.aligned.m16n8k16.row.col.f32.f16.f16.f32 "
        "{%0,%1,%2,%3}, {%4,%5,%6,%7}, {%8,%9}, {%0,%1,%2,%3};"
        : "+f"(d[0]), "+f"(d[1]), "+f"(d[2]), "+f"(d[3])
        : "r"(a[0]), "r"(a[1]), "r"(a[2]), "r"(a[3]), "r"(b[0]), "r"(b[1]));
}

// temp arrives as 1-elem scalar, int32 or float32 bits; decode robustly.
__device__ __forceinline__ float decode_scalar(const int* p) {
    int ib = *p;
    float f = __int_as_float(ib);
    if (isfinite(f) && fabsf(f) > 1e-30f && fabsf(f) < 1e30f) return f;
    return (float)ib;
}

// ---------------------------------------------------------------------------
// c[b,i,j]: 8 rows per block, 256 threads; fp16 store. (identical to R8)
// ---------------------------------------------------------------------------
__global__ void __launch_bounds__(256) compute_c_kernel(
    const float* __restrict__ x, const float* __restrict__ w1,
    const float* __restrict__ b1, const float* __restrict__ w2)
{
    int b  = blockIdx.y;
    int i0 = blockIdx.x * 8;
    __shared__ float xs[NN];
    __shared__ float sw1a[16], sw1b[16], sb1[16], sw2[16];
    int t = threadIdx.x;
    if (t < 16) {
        sw1a[t] = w1[t * 2 + 0];
        sw1b[t] = w1[t * 2 + 1];
        sb1[t]  = b1[t];
        sw2[t]  = w2[t];
    }
    xs[t]       = x[b * NN + t];
    xs[t + 256] = x[b * NN + t + 256];
    __syncthreads();

    for (int ii = 0; ii < 8; ii++) {
        int i = i0 + ii;
        float xi = xs[i];
        size_t rowoff = ((size_t)b * NN + i) * NN;
        for (int j = t; j < NN; j += 256) {
            float xj = xs[j];
            float s = 0.f;
#pragma unroll
            for (int o = 0; o < 16; o++) {
                float h1 = fmaxf(fmaf(sw1a[o], xi, fmaf(sw1b[o], xj, sb1[o])), 0.f);
                float h2 = fmaxf(fmaf(sw1a[o], xj, fmaf(sw1b[o], xi, sb1[o])), 0.f);
                s = fmaf(sw2[o], h1 - h2, s);
            }
            g_c16[rowoff + j] = __float2half(s);
        }
    }
}

// ---------------------------------------------------------------------------
// Step 0 fused (a0 uniform). Writes a16 ping. (identical math to R8)
// ---------------------------------------------------------------------------
__global__ void __launch_bounds__(512) step0_kernel(
    const float* __restrict__ lr, const int* __restrict__ temp_p)
{
    const int row  = blockIdx.x;
    const int k    = threadIdx.x;
    const int lane = k & 31;
    const int wid  = k >> 5;
    size_t off = (size_t)row * NN + k;

    __shared__ float red[16];

    float v = __half2float(g_c16[off]);
#pragma unroll
    for (int o = 16; o > 0; o >>= 1) v += __shfl_xor_sync(0xffffffffu, v, o);
    if (lane == 0) red[wid] = v;
    __syncthreads();
    if (wid == 0) {
        float s = (lane < 16) ? red[lane] : 0.f;
#pragma unroll
        for (int o = 16; o > 0; o >>= 1) s += __shfl_xor_sync(0xffffffffu, s, o);
        if (lane == 0) red[0] = s;
    }
    __syncthreads();
    const float S = red[0];
    __syncthreads();

    const float lr_abs = fabsf(lr[0]);
    const float invT   = 1.f / decode_scalar(temp_p);
    const float invN   = 1.f / (float)NN;
    float logit = (invN - lr_abs * S * (1.f - (2.f * k + 1.f) * invN)) * invT;

    float m = logit;
#pragma unroll
    for (int o = 16; o > 0; o >>= 1) m = fmaxf(m, __shfl_xor_sync(0xffffffffu, m, o));
    if (lane == 0) red[wid] = m;
    __syncthreads();
    if (wid == 0) {
        float mm = (lane < 16) ? red[lane] : -INFINITY;
#pragma unroll
        for (int o = 16; o > 0; o >>= 1) mm = fmaxf(mm, __shfl_xor_sync(0xffffffffu, mm, o));
        if (lane == 0) red[0] = mm;
    }
    __syncthreads();
    m = red[0];
    __syncthreads();
    float e = __expf(logit - m);
    float s = e;
#pragma unroll
    for (int o = 16; o > 0; o >>= 1) s += __shfl_xor_sync(0xffffffffu, s, o);
    if (lane == 0) red[wid] = s;
    __syncthreads();
    if (wid == 0) {
        float ss = (lane < 16) ? red[lane] : 0.f;
#pragma unroll
        for (int o = 16; o > 0; o >>= 1) ss += __shfl_xor_sync(0xffffffffu, ss, o);
        if (lane == 0) red[0] = ss;
    }
    __syncthreads();
    g_a16a[off] = __float2half(e / red[0]);
}

// ---------------------------------------------------------------------------
// Fused step: CTA tile 64 rows x 512 cols (two 256-col halves), 256 thr
// (8 warps, 2M x 4N per half, warp tile 32x64). 2 CTAs/SM. G never touches
// global. Reads a16[in], writes a16[out] (+ fp32 a on last step).
// Numerics identical to R8/R10.
// ---------------------------------------------------------------------------
#define PAE 40                            // A pitch (fp16), K=32 stage rows of 80B
#define PBE 264                           // B pitch (fp16), 256-col rows of 528B
#define A_ST (64 * PAE * 2)               // 5120 B
#define B_ST (32 * PBE * 2)               // 16896 B
#define NST 2
#define AR_OFF 0
#define BR_OFF (NST * A_ST)               // 10240
#define G0_OFF (BR_OFF + NST * B_ST)      // 44032
#define GP 260                            // G smem pitch (floats)
#define FUSE_SMEM (G0_OFF + 64 * GP * 4)  // 110592 (108 KB) -> 2 CTAs/SM

__global__ void __launch_bounds__(256, 2) fused_step_kernel(
    const __half* __restrict__ ain, __half* __restrict__ aout,
    float* __restrict__ a_f32, const float* __restrict__ lr,
    const int* __restrict__ temp_p, int last)
{
    extern __shared__ __align__(16) char sm[];
    const int b  = blockIdx.y;
    const int m0 = blockIdx.x * 64;
    const int tid  = threadIdx.x;
    const int wid  = tid >> 5;
    const int lane = tid & 31;

    const __half* Amat = g_c16 + (size_t)b * NN * NN;
    const __half* Bmat = ain   + (size_t)b * NN * NN;

    const uint32_t smbase = smem_u32(sm);
    float* G0 = (float*)(sm + G0_OFF);     // 64 x GP, half-0 G
    float* GC = (float*)sm;                // 32 x GP chunk, aliases rings

    const int wm = wid & 1;                // M half (32 rows)
    const int wn = wid >> 1;               // N quarter (64 cols of the 256 half)
    const int l_r = lane & 15;
    const int l_c = 8 * (lane >> 4);

    float acc[2][8][4];

    auto load_stage = [&](int st, int half) {
        const int k0 = st * 32;
        const uint32_t sbA = smbase + AR_OFF + (st % NST) * A_ST;
        const uint32_t sbB = smbase + BR_OFF + (st % NST) * B_ST;
        {   // A: 64 rows x 32k = 256 chunks, 1/thread
            int r = tid >> 2, c = tid & 3;
            cp_async16(sbA + (uint32_t)(r * (PAE * 2) + c * 16),
                       Amat + (size_t)(m0 + r) * NN + k0 + c * 8);
        }
#pragma unroll
        for (int it = 0; it < 4; it++) {   // B: 32k x 256n = 1024 chunks
            int idx = it * 256 + tid;
            int r = idx >> 5, c = idx & 31;
            cp_async16(sbB + (uint32_t)(r * (PBE * 2) + c * 16),
                       Bmat + (size_t)(k0 + r) * NN + half * 256 + c * 8);
        }
        cp_commit();
    };

    auto compute_stage = [&](int st) {
        const uint32_t sbA = smbase + AR_OFF + (st % NST) * A_ST;
        const uint32_t sbB = smbase + BR_OFF + (st % NST) * B_ST;
#pragma unroll
        for (int ks = 0; ks < 2; ks++) {
            const int kb = ks * 16;
            uint32_t ah[2][4];
#pragma unroll
            for (int mi = 0; mi < 2; mi++) {
                uint32_t addr = sbA + (wm * 32 + mi * 16 + l_r) * (PAE * 2) + (kb + l_c) * 2;
                ldsm_x4(ah[mi], addr);
            }
            uint32_t bh[8][2];
#pragma unroll
            for (int nh = 0; nh < 2; nh++) {
#pragma unroll
                for (int t16 = 0; t16 < 2; t16++) {
                    uint32_t addr = sbB + (kb + l_r) * (PBE * 2) +
                                    (wn * 64 + nh * 32 + t16 * 16 + l_c) * 2;
                    uint32_t r4[4];
                    ldsm_x4_t(r4, addr);
                    int base = nh * 4 + t16 * 2;
                    bh[base][0] = r4[0];     bh[base][1] = r4[1];
                    bh[base + 1][0] = r4[2]; bh[base + 1][1] = r4[3];
                }
            }
#pragma unroll
            for (int mi = 0; mi < 2; mi++)
#pragma unroll
                for (int ni = 0; ni < 8; ni++)
                    mma_fp16(acc[mi][ni], ah[mi], bh[ni]);
        }
    };

#pragma unroll
    for (int half = 0; half < 2; half++) {
#pragma unroll
        for (int mi = 0; mi < 2; mi++)
#pragma unroll
            for (int ni = 0; ni < 8; ni++)
#pragma unroll
                for (int q = 0; q < 4; q++) acc[mi][ni][q] = 0.f;

        load_stage(0, half);
        for (int s = 0; s < 16; s++) {
            cp_wait0();
            __syncthreads();
            if (s + 1 < 16) load_stage(s + 1, half);   // other buffer; safe after sync
            compute_stage(s);
        }
        __syncthreads();   // all compute done; rings reusable

        if (half == 0) {
            // stage half-0 G into G0 smem
#pragma unroll
            for (int mi = 0; mi < 2; mi++) {
                int r = wm * 32 + mi * 16 + (lane >> 2);
#pragma unroll
                for (int ni = 0; ni < 8; ni++) {
                    int col = wn * 64 + ni * 8 + (lane & 3) * 2;
                    *(float2*)(G0 + r * GP + col) =
                        make_float2(acc[mi][ni][0], acc[mi][ni][1]);
                    *(float2*)(G0 + (r + 8) * GP + col) =
                        make_float2(acc[mi][ni][2], acc[mi][ni][3]);
                }
            }
        }
    }

    // ---- epilogue (rows in two groups of 32; half-1 G dumped into GC) ----
    const float lr_abs = fabsf(lr[0]);
    const float invT   = 1.f / decode_scalar(temp_p);

    for (int grp = 0; grp < 2; grp++) {
        __syncthreads();
        if (wm == grp) {
#pragma unroll
            for (int mi = 0; mi < 2; mi++) {
                int r = mi * 16 + (lane >> 2);    // group-local 0..31
#pragma unroll
                for (int ni = 0; ni < 8; ni++) {
                    int col = wn * 64 + ni * 8 + (lane & 3) * 2;
                    *(float2*)(GC + r * GP + col) =
                        make_float2(acc[mi][ni][0], acc[mi][ni][1]);
                    *(float2*)(GC + (r + 8) * GP + col) =
                        make_float2(acc[mi][ni][2], acc[mi][ni][3]);
                }
            }
        }
        __syncthreads();

        for (int j = 0; j < 4; j++) {
            const int rr = grp * 32 + wid * 4 + j;          // 0..63
            const size_t gbase = ((size_t)(b * NN + m0 + rr)) * NN + lane * 16;

            float g[16];
            if (lane < 16) {
                const float* src = G0 + rr * GP + lane * 16;
#pragma unroll
                for (int q = 0; q < 4; q++) {
                    float4 v = *(const float4*)(src + q * 4);
                    g[q * 4 + 0] = v.x; g[q * 4 + 1] = v.y;
                    g[q * 4 + 2] = v.z; g[q * 4 + 3] = v.w;
                }
            } else {
                const float* src = GC + (rr - grp * 32) * GP + (lane * 16 - 256);
#pragma unroll
                for (int q = 0; q < 4; q++) {
                    float4 v = *(const float4*)(src + q * 4);
                    g[q * 4 + 0] = v.x; g[q * 4 + 1] = v.y;
                    g[q * 4 + 2] = v.z; g[q * 4 + 3] = v.w;
                }
            }

            union U16 { uint4 u4[2]; __half h[16]; };
            U16 ua;
            ua.u4[0] = *(const uint4*)(ain + gbase);
            ua.u4[1] = *(const uint4*)(ain + gbase + 8);

            float av[16];
#pragma unroll
            for (int c = 0; c < 16; c++) av[c] = __half2float(ua.h[c]);

            float p[16];
            float run = 0.f;
#pragma unroll
            for (int c = 0; c < 16; c++) { run += g[c]; p[c] = run; }
            float inc = run;
#pragma unroll
            for (int o = 1; o < 32; o <<= 1) {
                float n = __shfl_up_sync(0xffffffffu, inc, o);
                if (lane >= o) inc += n;
            }
            const float excl = inc - run;

            float lo[16];
            float mx = -INFINITY;
#pragma unroll
            for (int c = 0; c < 16; c++) {
                float cum = excl + p[c];
                float l = (av[c] - lr_abs * (g[c] - 2.f * cum)) * invT;
                lo[c] = l;
                mx = fmaxf(mx, l);
            }
#pragma unroll
            for (int o = 16; o > 0; o >>= 1) mx = fmaxf(mx, __shfl_xor_sync(0xffffffffu, mx, o));

            float s = 0.f;
#pragma unroll
            for (int c = 0; c < 16; c++) { lo[c] = __expf(lo[c] - mx); s += lo[c]; }
#pragma unroll
            for (int o = 16; o > 0; o >>= 1) s += __shfl_xor_sync(0xffffffffu, s, o);
            const float invS = 1.f / s;

            U16 oa;
#pragma unroll
            for (int c = 0; c < 16; c++) {
                float v = lo[c] * invS;
                oa.h[c] = __float2half(v);
                lo[c] = v;
            }
            *(uint4*)(aout + gbase)     = oa.u4[0];
            *(uint4*)(aout + gbase + 8) = oa.u4[1];

            if (last) {
                float* ar = a_f32 + gbase;
#pragma unroll
                for (int q = 0; q < 4; q++)
                    *(float4*)(ar + q * 4) = make_float4(lo[q * 4 + 0], lo[q * 4 + 1],
                                                         lo[q * 4 + 2], lo[q * 4 + 3]);
            }
        }
    }
}

// ---------------------------------------------------------------------------
// y[b,k] = sum_i x[b,i] * a[b,i,k]; 16 i-chunks per batch + atomicAdd.
// ---------------------------------------------------------------------------
__global__ void init_y_kernel(float* __restrict__ y)
{
    y[blockIdx.x * 1024 + threadIdx.x] = 0.f;
}

__global__ void __launch_bounds__(512) y_kernel(
    const float* __restrict__ x, const float* __restrict__ a, float* __restrict__ y)
{
    int b  = blockIdx.x;
    int ch = blockIdx.y;
    int k  = threadIdx.x;
    __shared__ float xs[32];
    if (k < 32) xs[k] = x[b * NN + ch * 32 + k];
    __syncthreads();
    const float* ab = a + (size_t)b * NN * NN + (size_t)ch * 32 * NN;
    float a0 = 0.f, a1 = 0.f, a2 = 0.f, a3 = 0.f;
#pragma unroll
    for (int i = 0; i < 32; i += 4) {
        a0 = fmaf(xs[i + 0], ab[(size_t)(i + 0) * NN + k], a0);
        a1 = fmaf(xs[i + 1], ab[(size_t)(i + 1) * NN + k], a1);
        a2 = fmaf(xs[i + 2], ab[(size_t)(i + 2) * NN + k], a2);
        a3 = fmaf(xs[i + 3], ab[(size_t)(i + 3) * NN + k], a3);
    }
    atomicAdd(&y[b * NN + k], (a0 + a1) + (a2 + a3));
}

// ---------------------------------------------------------------------------
extern "C" void kernel_launch(void* const* d_in, const int* in_sizes, int n_in,
                              void* d_out, int out_size)
{
    const float* x   = (const float*)d_in[0];
    const float* w1  = (const float*)d_in[1];
    const float* b1  = (const float*)d_in[2];
    const float* w2  = (const float*)d_in[3];
    // d_in[4] = b2 (cancels in c - c^T), d_in[6] = steps (fixed at 8)
    const float* lr  = (const float*)d_in[5];
    const int* temp_p = (const int*)d_in[7];

    float* y = (float*)d_out;              // (32,1,512)
    float* a = (float*)d_out + NB * NN;    // (32,512,512), written on last step

    cudaFuncSetAttribute(fused_step_kernel,
                         cudaFuncAttributeMaxDynamicSharedMemorySize, FUSE_SMEM);

    compute_c_kernel<<<dim3(NN / 8, NB), 256>>>(x, w1, b1, w2);
    step0_kernel<<<NB * NN, 512>>>(lr, temp_p);

    __half* bufs[2];
    cudaGetSymbolAddress((void**)&bufs[0], g_a16a);
    cudaGetSymbolAddress((void**)&bufs[1], g_a16b);

    for (int s = 0; s < 7; s++) {
        fused_step_kernel<<<dim3(8, NB), 256, FUSE_SMEM>>>(
            bufs[s & 1], bufs[(s + 1) & 1], a, lr, temp_p, (s == 6) ? 1 : 0);
    }

    init_y_kernel<<<NB * NN / 1024, 1024>>>(y);
    y_kernel<<<dim3(NB, 16), 512>>>(x, a, y);
}

// round 12
// speedup vs baseline: 1.0069x; 1.0069x over previous
#include <cuda_runtime.h>
#include <cuda_fp16.h>
#include <math.h>
#include <cstdint>

#define NB 32
#define NN 512

// Scratch (device globals; allocation-free per harness rules).
__device__ __align__(16) __half g_c16[(size_t)NB * NN * NN];   // fp16 c [m][k]
__device__ __align__(16) __half g_a16a[(size_t)NB * NN * NN];  // fp16 a ping
__device__ __align__(16) __half g_a16b[(size_t)NB * NN * NN];  // fp16 a pong

// Grid barrier state (persistent kernel)
__device__ unsigned g_bcount = 0;
__device__ volatile unsigned g_bgen = 0;

// ---------------------------------------------------------------------------
__device__ __forceinline__ uint32_t smem_u32(const void* p) {
    uint32_t a;
    asm("{ .reg .u64 t; cvta.to.shared.u64 t, %1; cvt.u32.u64 %0, t; }" : "=r"(a) : "l"(p));
    return a;
}
__device__ __forceinline__ void cp_async16(uint32_t saddr, const void* gaddr) {
    asm volatile("cp.async.cg.shared.global [%0], [%1], 16;" :: "r"(saddr), "l"(gaddr) : "memory");
}
__device__ __forceinline__ void cp_commit() { asm volatile("cp.async.commit_group;" ::: "memory"); }
__device__ __forceinline__ void cp_wait0()  { asm volatile("cp.async.wait_group 0;" ::: "memory"); }
__device__ __forceinline__ void ldsm_x4(uint32_t* r, uint32_t addr) {
    asm volatile("ldmatrix.sync.aligned.m8n8.x4.shared.b16 {%0,%1,%2,%3}, [%4];"
                 : "=r"(r[0]), "=r"(r[1]), "=r"(r[2]), "=r"(r[3]) : "r"(addr));
}
__device__ __forceinline__ void ldsm_x4_t(uint32_t* r, uint32_t addr) {
    asm volatile("ldmatrix.sync.aligned.m8n8.x4.trans.shared.b16 {%0,%1,%2,%3}, [%4];"
                 : "=r"(r[0]), "=r"(r[1]), "=r"(r[2]), "=r"(r[3]) : "r"(addr));
}
__device__ __forceinline__ void mma_fp16(float* d, const uint32_t* a, const uint32_t* b) {
    asm volatile(
        "mma.sync.aligned.m16n8k16.row.col.f32.f16.f16.f32 "
        "{%0,%1,%2,%3}, {%4,%5,%6,%7}, {%8,%9}, {%0,%1,%2,%3};"
        : "+f"(d[0]), "+f"(d[1]), "+f"(d[2]), "+f"(d[3])
        : "r"(a[0]), "r"(a[1]), "r"(a[2]), "r"(a[3]), "r"(b[0]), "r"(b[1]));
}

// temp arrives as 1-elem scalar, int32 or float32 bits; decode robustly.
__device__ __forceinline__ float decode_scalar(const int* p) {
    int ib = *p;
    float f = __int_as_float(ib);
    if (isfinite(f) && fabsf(f) > 1e-30f && fabsf(f) < 1e30f) return f;
    return (float)ib;
}

// ---------------------------------------------------------------------------
// c[b,i,j]: 8 rows per block, 256 threads; fp16 store. (identical to R8)
// ---------------------------------------------------------------------------
__global__ void __launch_bounds__(256) compute_c_kernel(
    const float* __restrict__ x, const float* __restrict__ w1,
    const float* __restrict__ b1, const float* __restrict__ w2)
{
    int b  = blockIdx.y;
    int i0 = blockIdx.x * 8;
    __shared__ float xs[NN];
    __shared__ float sw1a[16], sw1b[16], sb1[16], sw2[16];
    int t = threadIdx.x;
    if (t < 16) {
        sw1a[t] = w1[t * 2 + 0];
        sw1b[t] = w1[t * 2 + 1];
        sb1[t]  = b1[t];
        sw2[t]  = w2[t];
    }
    xs[t]       = x[b * NN + t];
    xs[t + 256] = x[b * NN + t + 256];
    __syncthreads();

    for (int ii = 0; ii < 8; ii++) {
        int i = i0 + ii;
        float xi = xs[i];
        size_t rowoff = ((size_t)b * NN + i) * NN;
        for (int j = t; j < NN; j += 256) {
            float xj = xs[j];
            float s = 0.f;
#pragma unroll
            for (int o = 0; o < 16; o++) {
                float h1 = fmaxf(fmaf(sw1a[o], xi, fmaf(sw1b[o], xj, sb1[o])), 0.f);
                float h2 = fmaxf(fmaf(sw1a[o], xj, fmaf(sw1b[o], xi, sb1[o])), 0.f);
                s = fmaf(sw2[o], h1 - h2, s);
            }
            g_c16[rowoff + j] = __float2half(s);
        }
    }
}

// ---------------------------------------------------------------------------
// Step 0 fused (a0 uniform). Writes a16 ping. (identical math to R8)
// ---------------------------------------------------------------------------
__global__ void __launch_bounds__(512) step0_kernel(
    const float* __restrict__ lr, const int* __restrict__ temp_p)
{
    const int row  = blockIdx.x;
    const int k    = threadIdx.x;
    const int lane = k & 31;
    const int wid  = k >> 5;
    size_t off = (size_t)row * NN + k;

    __shared__ float red[16];

    float v = __half2float(g_c16[off]);
#pragma unroll
    for (int o = 16; o > 0; o >>= 1) v += __shfl_xor_sync(0xffffffffu, v, o);
    if (lane == 0) red[wid] = v;
    __syncthreads();
    if (wid == 0) {
        float s = (lane < 16) ? red[lane] : 0.f;
#pragma unroll
        for (int o = 16; o > 0; o >>= 1) s += __shfl_xor_sync(0xffffffffu, s, o);
        if (lane == 0) red[0] = s;
    }
    __syncthreads();
    const float S = red[0];
    __syncthreads();

    const float lr_abs = fabsf(lr[0]);
    const float invT   = 1.f / decode_scalar(temp_p);
    const float invN   = 1.f / (float)NN;
    float logit = (invN - lr_abs * S * (1.f - (2.f * k + 1.f) * invN)) * invT;

    float m = logit;
#pragma unroll
    for (int o = 16; o > 0; o >>= 1) m = fmaxf(m, __shfl_xor_sync(0xffffffffu, m, o));
    if (lane == 0) red[wid] = m;
    __syncthreads();
    if (wid == 0) {
        float mm = (lane < 16) ? red[lane] : -INFINITY;
#pragma unroll
        for (int o = 16; o > 0; o >>= 1) mm = fmaxf(mm, __shfl_xor_sync(0xffffffffu, mm, o));
        if (lane == 0) red[0] = mm;
    }
    __syncthreads();
    m = red[0];
    __syncthreads();
    float e = __expf(logit - m);
    float s = e;
#pragma unroll
    for (int o = 16; o > 0; o >>= 1) s += __shfl_xor_sync(0xffffffffu, s, o);
    if (lane == 0) red[wid] = s;
    __syncthreads();
    if (wid == 0) {
        float ss = (lane < 16) ? red[lane] : 0.f;
#pragma unroll
        for (int o = 16; o > 0; o >>= 1) ss += __shfl_xor_sync(0xffffffffu, ss, o);
        if (lane == 0) red[0] = ss;
    }
    __syncthreads();
    g_a16a[off] = __float2half(e / red[0]);
}

// ---------------------------------------------------------------------------
// Persistent 7-step kernel: R11 fused body (bitwise identical numerics)
// looped in-kernel with a software grid barrier between steps.
// grid = 8 x 32 = 256 CTAs, all resident at 2 CTAs/SM (296 slots).
// ---------------------------------------------------------------------------
#define PAE 40                            // A pitch (fp16), K=32 stage rows of 80B
#define PBE 264                           // B pitch (fp16), 256-col rows of 528B
#define A_ST (64 * PAE * 2)               // 5120 B
#define B_ST (32 * PBE * 2)               // 16896 B
#define NST 2
#define AR_OFF 0
#define BR_OFF (NST * A_ST)               // 10240
#define G0_OFF (BR_OFF + NST * B_ST)      // 44032
#define GP 260                            // G smem pitch (floats)
#define FUSE_SMEM (G0_OFF + 64 * GP * 4)  // 110592 (108 KB) -> 2 CTAs/SM

__device__ __forceinline__ void grid_sync_all(unsigned nctas)
{
    __threadfence();
    __syncthreads();
    if (threadIdx.x == 0) {
        unsigned gen = g_bgen;
        if (atomicAdd(&g_bcount, 1u) == nctas - 1u) {
            g_bcount = 0;
            __threadfence();
            g_bgen = gen + 1u;
        } else {
            while (g_bgen == gen) __nanosleep(64);
        }
    }
    __syncthreads();
}

__global__ void __launch_bounds__(256, 2) persistent_steps_kernel(
    float* __restrict__ a_f32, const float* __restrict__ lr,
    const int* __restrict__ temp_p)
{
    extern __shared__ __align__(16) char sm[];
    const int b  = blockIdx.y;
    const int m0 = blockIdx.x * 64;
    const int tid  = threadIdx.x;
    const int wid  = tid >> 5;
    const int lane = tid & 31;
    const unsigned nctas = gridDim.x * gridDim.y;

    const __half* Amat = g_c16 + (size_t)b * NN * NN;

    const uint32_t smbase = smem_u32(sm);
    float* G0 = (float*)(sm + G0_OFF);     // 64 x GP, half-0 G
    float* GC = (float*)sm;                // 32 x GP chunk, aliases rings

    const int wm = wid & 1;                // M half (32 rows)
    const int wn = wid >> 1;               // N quarter (64 cols of the 256 half)
    const int l_r = lane & 15;
    const int l_c = 8 * (lane >> 4);

    const float lr_abs = fabsf(lr[0]);
    const float invT   = 1.f / decode_scalar(temp_p);

    for (int step = 0; step < 7; step++) {
        const __half* ain = (step & 1) ? g_a16b : g_a16a;
        __half*       aout = (step & 1) ? g_a16a : g_a16b;
        const int last = (step == 6);
        const __half* Bmat = ain + (size_t)b * NN * NN;

        float acc[2][8][4];

        auto load_stage = [&](int st, int half) {
            const int k0 = st * 32;
            const uint32_t sbA = smbase + AR_OFF + (st % NST) * A_ST;
            const uint32_t sbB = smbase + BR_OFF + (st % NST) * B_ST;
            {   // A: 64 rows x 32k = 256 chunks, 1/thread
                int r = tid >> 2, c = tid & 3;
                cp_async16(sbA + (uint32_t)(r * (PAE * 2) + c * 16),
                           Amat + (size_t)(m0 + r) * NN + k0 + c * 8);
            }
#pragma unroll
            for (int it = 0; it < 4; it++) {   // B: 32k x 256n = 1024 chunks
                int idx = it * 256 + tid;
                int r = idx >> 5, c = idx & 31;
                cp_async16(sbB + (uint32_t)(r * (PBE * 2) + c * 16),
                           Bmat + (size_t)(k0 + r) * NN + half * 256 + c * 8);
            }
            cp_commit();
        };

        auto compute_stage = [&](int st) {
            const uint32_t sbA = smbase + AR_OFF + (st % NST) * A_ST;
            const uint32_t sbB = smbase + BR_OFF + (st % NST) * B_ST;
#pragma unroll
            for (int ks = 0; ks < 2; ks++) {
                const int kb = ks * 16;
                uint32_t ah[2][4];
#pragma unroll
                for (int mi = 0; mi < 2; mi++) {
                    uint32_t addr = sbA + (wm * 32 + mi * 16 + l_r) * (PAE * 2) + (kb + l_c) * 2;
                    ldsm_x4(ah[mi], addr);
                }
                uint32_t bh[8][2];
#pragma unroll
                for (int nh = 0; nh < 2; nh++) {
#pragma unroll
                    for (int t16 = 0; t16 < 2; t16++) {
                        uint32_t addr = sbB + (kb + l_r) * (PBE * 2) +
                                        (wn * 64 + nh * 32 + t16 * 16 + l_c) * 2;
                        uint32_t r4[4];
                        ldsm_x4_t(r4, addr);
                        int base = nh * 4 + t16 * 2;
                        bh[base][0] = r4[0];     bh[base][1] = r4[1];
                        bh[base + 1][0] = r4[2]; bh[base + 1][1] = r4[3];
                    }
                }
#pragma unroll
                for (int mi = 0; mi < 2; mi++)
#pragma unroll
                    for (int ni = 0; ni < 8; ni++)
                        mma_fp16(acc[mi][ni], ah[mi], bh[ni]);
            }
        };

#pragma unroll
        for (int half = 0; half < 2; half++) {
#pragma unroll
            for (int mi = 0; mi < 2; mi++)
#pragma unroll
                for (int ni = 0; ni < 8; ni++)
#pragma unroll
                    for (int q = 0; q < 4; q++) acc[mi][ni][q] = 0.f;

            load_stage(0, half);
            for (int s = 0; s < 16; s++) {
                cp_wait0();
                __syncthreads();
                if (s + 1 < 16) load_stage(s + 1, half);   // other buffer; safe after sync
                compute_stage(s);
            }
            __syncthreads();   // all compute done; rings reusable

            if (half == 0) {
                // stage half-0 G into G0 smem
#pragma unroll
                for (int mi = 0; mi < 2; mi++) {
                    int r = wm * 32 + mi * 16 + (lane >> 2);
#pragma unroll
                    for (int ni = 0; ni < 8; ni++) {
                        int col = wn * 64 + ni * 8 + (lane & 3) * 2;
                        *(float2*)(G0 + r * GP + col) =
                            make_float2(acc[mi][ni][0], acc[mi][ni][1]);
                        *(float2*)(G0 + (r + 8) * GP + col) =
                            make_float2(acc[mi][ni][2], acc[mi][ni][3]);
                    }
                }
            }
        }

        // ---- epilogue (rows in two groups of 32; half-1 G dumped into GC) ----
        for (int grp = 0; grp < 2; grp++) {
            __syncthreads();
            if (wm == grp) {
#pragma unroll
                for (int mi = 0; mi < 2; mi++) {
                    int r = mi * 16 + (lane >> 2);    // group-local 0..31
#pragma unroll
                    for (int ni = 0; ni < 8; ni++) {
                        int col = wn * 64 + ni * 8 + (lane & 3) * 2;
                        *(float2*)(GC + r * GP + col) =
                            make_float2(acc[mi][ni][0], acc[mi][ni][1]);
                        *(float2*)(GC + (r + 8) * GP + col) =
                            make_float2(acc[mi][ni][2], acc[mi][ni][3]);
                    }
                }
            }
            __syncthreads();

            for (int j = 0; j < 4; j++) {
                const int rr = grp * 32 + wid * 4 + j;          // 0..63
                const size_t gbase = ((size_t)(b * NN + m0 + rr)) * NN + lane * 16;

                float g[16];
                if (lane < 16) {
                    const float* src = G0 + rr * GP + lane * 16;
#pragma unroll
                    for (int q = 0; q < 4; q++) {
                        float4 v = *(const float4*)(src + q * 4);
                        g[q * 4 + 0] = v.x; g[q * 4 + 1] = v.y;
                        g[q * 4 + 2] = v.z; g[q * 4 + 3] = v.w;
                    }
                } else {
                    const float* src = GC + (rr - grp * 32) * GP + (lane * 16 - 256);
#pragma unroll
                    for (int q = 0; q < 4; q++) {
                        float4 v = *(const float4*)(src + q * 4);
                        g[q * 4 + 0] = v.x; g[q * 4 + 1] = v.y;
                        g[q * 4 + 2] = v.z; g[q * 4 + 3] = v.w;
                    }
                }

                union U16 { uint4 u4[2]; __half h[16]; };
                U16 ua;
                ua.u4[0] = *(const uint4*)(ain + gbase);
                ua.u4[1] = *(const uint4*)(ain + gbase + 8);

                float av[16];
#pragma unroll
                for (int c = 0; c < 16; c++) av[c] = __half2float(ua.h[c]);

                float p[16];
                float run = 0.f;
#pragma unroll
                for (int c = 0; c < 16; c++) { run += g[c]; p[c] = run; }
                float inc = run;
#pragma unroll
                for (int o = 1; o < 32; o <<= 1) {
                    float n = __shfl_up_sync(0xffffffffu, inc, o);
                    if (lane >= o) inc += n;
                }
                const float excl = inc - run;

                float lo[16];
                float mx = -INFINITY;
#pragma unroll
                for (int c = 0; c < 16; c++) {
                    float cum = excl + p[c];
                    float l = (av[c] - lr_abs * (g[c] - 2.f * cum)) * invT;
                    lo[c] = l;
                    mx = fmaxf(mx, l);
                }
#pragma unroll
                for (int o = 16; o > 0; o >>= 1) mx = fmaxf(mx, __shfl_xor_sync(0xffffffffu, mx, o));

                float s = 0.f;
#pragma unroll
                for (int c = 0; c < 16; c++) { lo[c] = __expf(lo[c] - mx); s += lo[c]; }
#pragma unroll
                for (int o = 16; o > 0; o >>= 1) s += __shfl_xor_sync(0xffffffffu, s, o);
                const float invS = 1.f / s;

                U16 oa;
#pragma unroll
                for (int c = 0; c < 16; c++) {
                    float v = lo[c] * invS;
                    oa.h[c] = __float2half(v);
                    lo[c] = v;
                }
                *(uint4*)(aout + gbase)     = oa.u4[0];
                *(uint4*)(aout + gbase + 8) = oa.u4[1];

                if (last) {
                    float* ar = a_f32 + gbase;
#pragma unroll
                    for (int q = 0; q < 4; q++)
                        *(float4*)(ar + q * 4) = make_float4(lo[q * 4 + 0], lo[q * 4 + 1],
                                                             lo[q * 4 + 2], lo[q * 4 + 3]);
                }
            }
        }

        if (step < 6) grid_sync_all(nctas);
    }
}

// ---------------------------------------------------------------------------
// y[b,k] = sum_i x[b,i] * a[b,i,k]; no atomics: block = (b, k-chunk of 128).
// ---------------------------------------------------------------------------
__global__ void __launch_bounds__(128) y_kernel(
    const float* __restrict__ x, const float* __restrict__ a, float* __restrict__ y)
{
    int b  = blockIdx.x;
    int k  = blockIdx.y * 128 + threadIdx.x;
    __shared__ float xs[NN];
    for (int i = threadIdx.x; i < NN; i += 128) xs[i] = x[b * NN + i];
    __syncthreads();
    const float* ab = a + (size_t)b * NN * NN;
    float a0 = 0.f, a1 = 0.f, a2 = 0.f, a3 = 0.f;
#pragma unroll 4
    for (int i = 0; i < NN; i += 4) {
        a0 = fmaf(xs[i + 0], ab[(size_t)(i + 0) * NN + k], a0);
        a1 = fmaf(xs[i + 1], ab[(size_t)(i + 1) * NN + k], a1);
        a2 = fmaf(xs[i + 2], ab[(size_t)(i + 2) * NN + k], a2);
        a3 = fmaf(xs[i + 3], ab[(size_t)(i + 3) * NN + k], a3);
    }
    y[b * NN + k] = (a0 + a1) + (a2 + a3);
}

// ---------------------------------------------------------------------------
extern "C" void kernel_launch(void* const* d_in, const int* in_sizes, int n_in,
                              void* d_out, int out_size)
{
    const float* x   = (const float*)d_in[0];
    const float* w1  = (const float*)d_in[1];
    const float* b1  = (const float*)d_in[2];
    const float* w2  = (const float*)d_in[3];
    // d_in[4] = b2 (cancels in c - c^T), d_in[6] = steps (fixed at 8)
    const float* lr  = (const float*)d_in[5];
    const int* temp_p = (const int*)d_in[7];

    float* y = (float*)d_out;              // (32,1,512)
    float* a = (float*)d_out + NB * NN;    // (32,512,512), written on last step

    cudaFuncSetAttribute(persistent_steps_kernel,
                         cudaFuncAttributeMaxDynamicSharedMemorySize, FUSE_SMEM);

    compute_c_kernel<<<dim3(NN / 8, NB), 256>>>(x, w1, b1, w2);
    step0_kernel<<<NB * NN, 512>>>(lr, temp_p);

    persistent_steps_kernel<<<dim3(8, NB), 256, FUSE_SMEM>>>(a, lr, temp_p);

    y_kernel<<<dim3(NB, 4), 128>>>(x, a, y);
}

// round 13
// speedup vs baseline: 1.1876x; 1.1795x over previous
#include <cuda_runtime.h>
#include <cuda_fp16.h>
#include <math.h>
#include <cstdint>

#define NB 32
#define NN 512

// Scratch (device globals; allocation-free per harness rules).
__device__ __align__(16) __half g_c16[(size_t)NB * NN * NN];  // fp16 c [m][k]
__device__ __align__(16) __half g_a16[(size_t)NB * NN * NN];  // fp16 a [j][n] row-major

// ---------------------------------------------------------------------------
__device__ __forceinline__ uint32_t smem_u32(const void* p) {
    uint32_t a;
    asm("{ .reg .u64 t; cvta.to.shared.u64 t, %1; cvt.u32.u64 %0, t; }" : "=r"(a) : "l"(p));
    return a;
}
__device__ __forceinline__ void cp_async16(uint32_t saddr, const void* gaddr) {
    asm volatile("cp.async.cg.shared.global [%0], [%1], 16;" :: "r"(saddr), "l"(gaddr) : "memory");
}
__device__ __forceinline__ void cp_commit() { asm volatile("cp.async.commit_group;" ::: "memory"); }
__device__ __forceinline__ void cp_wait6()  { asm volatile("cp.async.wait_group 6;" ::: "memory"); }
__device__ __forceinline__ void cp_wait0()  { asm volatile("cp.async.wait_group 0;" ::: "memory"); }
__device__ __forceinline__ void ldsm_x4(uint32_t* r, uint32_t addr) {
    asm volatile("ldmatrix.sync.aligned.m8n8.x4.shared.b16 {%0,%1,%2,%3}, [%4];"
                 : "=r"(r[0]), "=r"(r[1]), "=r"(r[2]), "=r"(r[3]) : "r"(addr));
}
__device__ __forceinline__ void ldsm_x4_t(uint32_t* r, uint32_t addr) {
    asm volatile("ldmatrix.sync.aligned.m8n8.x4.trans.shared.b16 {%0,%1,%2,%3}, [%4];"
                 : "=r"(r[0]), "=r"(r[1]), "=r"(r[2]), "=r"(r[3]) : "r"(addr));
}
__device__ __forceinline__ void mma_fp16(float* d, const uint32_t* a, const uint32_t* b) {
    asm volatile(
        "mma.sync.aligned.m16n8k16.row.col.f32.f16.f16.f32 "
        "{%0,%1,%2,%3}, {%4,%5,%6,%7}, {%8,%9}, {%0,%1,%2,%3};"
        : "+f"(d[0]), "+f"(d[1]), "+f"(d[2]), "+f"(d[3])
        : "r"(a[0]), "r"(a[1]), "r"(a[2]), "r"(a[3]), "r"(b[0]), "r"(b[1]));
}

// temp arrives as 1-elem scalar, int32 or float32 bits; decode robustly.
__device__ __forceinline__ float decode_scalar(const int* p) {
    int ib = *p;
    float f = __int_as_float(ib);
    if (isfinite(f) && fabsf(f) > 1e-30f && fabsf(f) < 1e30f) return f;
    return (float)ib;
}

// ---------------------------------------------------------------------------
// Fused c + step0: block owns 8 rows; computes c (fp16 store) AND the
// step-0 softmax (a0 uniform => closed form) entirely in-block.
// 256 threads; thread t handles cols t and t+256 of each row.
// ---------------------------------------------------------------------------
__global__ void __launch_bounds__(256) cstep0_kernel(
    const float* __restrict__ x, const float* __restrict__ w1,
    const float* __restrict__ b1, const float* __restrict__ w2,
    const float* __restrict__ lr, const int* __restrict__ temp_p)
{
    int b  = blockIdx.y;
    int i0 = blockIdx.x * 8;
    __shared__ float xs[NN];
    __shared__ float sw1a[16], sw1b[16], sb1[16], sw2[16];
    __shared__ float red[8];
    __shared__ float sS, sM, sT;
    const int t    = threadIdx.x;
    const int lane = t & 31;
    const int wid  = t >> 5;
    if (t < 16) {
        sw1a[t] = w1[t * 2 + 0];
        sw1b[t] = w1[t * 2 + 1];
        sb1[t]  = b1[t];
        sw2[t]  = w2[t];
    }
    xs[t]       = x[b * NN + t];
    xs[t + 256] = x[b * NN + t + 256];
    __syncthreads();

    const float lr_abs = fabsf(lr[0]);
    const float invT   = 1.f / decode_scalar(temp_p);
    const float invN   = 1.f / (float)NN;

    for (int ii = 0; ii < 8; ii++) {
        int i = i0 + ii;
        float xi = xs[i];
        size_t rowoff = ((size_t)b * NN + i) * NN;

        float sv[2];
#pragma unroll
        for (int q = 0; q < 2; q++) {
            float xj = xs[t + q * 256];
            float s = 0.f;
#pragma unroll
            for (int o = 0; o < 16; o++) {
                float h1 = fmaxf(fmaf(sw1a[o], xi, fmaf(sw1b[o], xj, sb1[o])), 0.f);
                float h2 = fmaxf(fmaf(sw1a[o], xj, fmaf(sw1b[o], xi, sb1[o])), 0.f);
                s = fmaf(sw2[o], h1 - h2, s);
            }
            __half h = __float2half(s);
            g_c16[rowoff + t + q * 256] = h;
            sv[q] = __half2float(h);
        }

        // rowsum S
        float v = sv[0] + sv[1];
#pragma unroll
        for (int o = 16; o > 0; o >>= 1) v += __shfl_xor_sync(0xffffffffu, v, o);
        if (lane == 0) red[wid] = v;
        __syncthreads();
        if (wid == 0) {
            float s8 = (lane < 8) ? red[lane] : 0.f;
#pragma unroll
            for (int o = 4; o > 0; o >>= 1) s8 += __shfl_xor_sync(0xffffffffu, s8, o);
            if (lane == 0) sS = s8;
        }
        __syncthreads();
        const float S = sS;

        // logits (k = t, t+256)
        float l0 = (invN - lr_abs * S * (1.f - (2.f * t + 1.f) * invN)) * invT;
        float l1 = (invN - lr_abs * S * (1.f - (2.f * (t + 256) + 1.f) * invN)) * invT;

        // block max
        float m = fmaxf(l0, l1);
#pragma unroll
        for (int o = 16; o > 0; o >>= 1) m = fmaxf(m, __shfl_xor_sync(0xffffffffu, m, o));
        __syncthreads();               // red reusable
        if (lane == 0) red[wid] = m;
        __syncthreads();
        if (wid == 0) {
            float m8 = (lane < 8) ? red[lane] : -INFINITY;
#pragma unroll
            for (int o = 4; o > 0; o >>= 1) m8 = fmaxf(m8, __shfl_xor_sync(0xffffffffu, m8, o));
            if (lane == 0) sM = m8;
        }
        __syncthreads();
        const float M = sM;

        float e0 = __expf(l0 - M);
        float e1 = __expf(l1 - M);
        float se = e0 + e1;
#pragma unroll
        for (int o = 16; o > 0; o >>= 1) se += __shfl_xor_sync(0xffffffffu, se, o);
        __syncthreads();
        if (lane == 0) red[wid] = se;
        __syncthreads();
        if (wid == 0) {
            float t8 = (lane < 8) ? red[lane] : 0.f;
#pragma unroll
            for (int o = 4; o > 0; o >>= 1) t8 += __shfl_xor_sync(0xffffffffu, t8, o);
            if (lane == 0) sT = t8;
        }
        __syncthreads();
        const float invTot = 1.f / sT;

        g_a16[rowoff + t]       = __float2half(e0 * invTot);
        g_a16[rowoff + t + 256] = __float2half(e1 * invTot);
        __syncthreads();               // red/sS reusable next row
    }
}

// ---------------------------------------------------------------------------
// Batched GEMM: G = c @ a, single-product fp16 mma.sync. (verbatim R8)
// 128 thr (4 warps, 2M x 2N, warp tile 64x64), block tile 128x128,
// 8-stage cp.async ring, K=16 per stage.
// ---------------------------------------------------------------------------
__device__ __align__(16) float g_G[(size_t)NB * NN * NN];

#define PA 24
#define PB 136
#define A_TILE_B (128 * PA * 2)        // 6144 B
#define B_TILE_B (16 * PB * 2)         // 4352 B
#define STAGE_B  (A_TILE_B + B_TILE_B) // 10496
#define NSTAGE 8
#define GEMM_SMEM (NSTAGE * STAGE_B)   // 83968

__global__ void __launch_bounds__(128, 2) gemm_mma_kernel()
{
    extern __shared__ __align__(16) char sm[];
    const int b  = blockIdx.z;
    const int m0 = blockIdx.y * 128;
    const int n0 = blockIdx.x * 128;
    const int tid  = threadIdx.x;
    const int wid  = tid >> 5;
    const int lane = tid & 31;

    const __half* Amat = g_c16 + (size_t)b * NN * NN;
    const __half* Bmat = g_a16 + (size_t)b * NN * NN;

    const uint32_t smbase = smem_u32(sm);

    auto load_stage = [&](int ks16) {
        const int k0 = ks16 * 16;
        const uint32_t sb = smbase + (ks16 % NSTAGE) * STAGE_B;
#pragma unroll
        for (int it = 0; it < 2; it++) {
            int idx = it * 128 + tid;
            int r   = idx >> 1;
            int c   = idx & 1;
            cp_async16(sb + (uint32_t)(r * (PA * 2) + c * 16),
                       Amat + (size_t)(m0 + r) * NN + k0 + c * 8);
        }
#pragma unroll
        for (int it = 0; it < 2; it++) {
            int idx = it * 128 + tid;
            int r   = idx >> 4;
            int c   = idx & 15;
            cp_async16(sb + A_TILE_B + (uint32_t)(r * (PB * 2) + c * 16),
                       Bmat + (size_t)(k0 + r) * NN + n0 + c * 8);
        }
        cp_commit();
    };

    const int wm = wid & 1;
    const int wn = wid >> 1;

    float acc[4][8][4];
#pragma unroll
    for (int mi = 0; mi < 4; mi++)
#pragma unroll
        for (int ni = 0; ni < 8; ni++)
#pragma unroll
            for (int q = 0; q < 4; q++) acc[mi][ni][q] = 0.f;

    const int l_r = lane & 15;
    const int l_c = 8 * (lane >> 4);

#pragma unroll
    for (int s = 0; s < NSTAGE - 1; s++) load_stage(s);

    for (int s = 0; s < 32; s++) {
        cp_wait6();
        __syncthreads();

        const uint32_t sb = smbase + (s % NSTAGE) * STAGE_B;
        uint32_t ah[4][4];
#pragma unroll
        for (int mi = 0; mi < 4; mi++) {
            uint32_t addr = sb + (wm * 64 + mi * 16 + l_r) * (PA * 2) + l_c * 2;
            ldsm_x4(ah[mi], addr);
        }
        uint32_t bh[8][2];
#pragma unroll
        for (int nh = 0; nh < 2; nh++) {
#pragma unroll
            for (int t16 = 0; t16 < 2; t16++) {
                uint32_t addr = sb + A_TILE_B +
                                l_r * (PB * 2) + (wn * 64 + nh * 32 + t16 * 16 + l_c) * 2;
                uint32_t r4[4];
                ldsm_x4_t(r4, addr);
                int base = nh * 4 + t16 * 2;
                bh[base][0] = r4[0];     bh[base][1] = r4[1];
                bh[base + 1][0] = r4[2]; bh[base + 1][1] = r4[3];
            }
        }
#pragma unroll
        for (int mi = 0; mi < 4; mi++)
#pragma unroll
            for (int ni = 0; ni < 8; ni++)
                mma_fp16(acc[mi][ni], ah[mi], bh[ni]);

        if (s + NSTAGE - 1 < 32) load_stage(s + NSTAGE - 1);
        __syncthreads();
    }
    cp_wait0();

    float* Gb = g_G + (size_t)b * NN * NN;
    const int g  = lane >> 2;
    const int t4 = lane & 3;
#pragma unroll
    for (int mi = 0; mi < 4; mi++) {
        int r0 = m0 + wm * 64 + mi * 16 + g;
#pragma unroll
        for (int ni = 0; ni < 8; ni++) {
            int col = n0 + wn * 64 + ni * 8 + t4 * 2;
            *(float2*)(Gb + (size_t)r0 * NN + col) =
                make_float2(acc[mi][ni][0], acc[mi][ni][1]);
            *(float2*)(Gb + (size_t)(r0 + 8) * NN + col) =
                make_float2(acc[mi][ni][2], acc[mi][ni][3]);
        }
    }
}

// ---------------------------------------------------------------------------
// Epilogue fused: warp per row; reads G + a(fp16); writes a' fp16
// (+ fp32 a' on last step).  (verbatim R8)
// ---------------------------------------------------------------------------
__global__ void __launch_bounds__(256) epi_fuse_kernel(
    float* __restrict__ a_out, const float* __restrict__ lr,
    const int* __restrict__ temp_p, int last)
{
    const int row  = blockIdx.x * 8 + (threadIdx.x >> 5);
    const int lane = threadIdx.x & 31;
    const size_t base = (size_t)row * NN + lane * 16;
    const float* Gr = g_G + base;

    float g[16];
#pragma unroll
    for (int q = 0; q < 4; q++) {
        float4 vg = *(const float4*)(Gr + q * 4);
        g[q * 4 + 0] = vg.x; g[q * 4 + 1] = vg.y; g[q * 4 + 2] = vg.z; g[q * 4 + 3] = vg.w;
    }

    union U16 { uint4 u4[2]; __half h[16]; };
    U16 ua;
    ua.u4[0] = *(const uint4*)(g_a16 + base);
    ua.u4[1] = *(const uint4*)(g_a16 + base + 8);

    float av[16];
#pragma unroll
    for (int c = 0; c < 16; c++) av[c] = __half2float(ua.h[c]);

    float p[16];
    float run = 0.f;
#pragma unroll
    for (int c = 0; c < 16; c++) { run += g[c]; p[c] = run; }
    float inc = run;
#pragma unroll
    for (int o = 1; o < 32; o <<= 1) {
        float n = __shfl_up_sync(0xffffffffu, inc, o);
        if (lane >= o) inc += n;
    }
    const float excl = inc - run;

    const float lr_abs = fabsf(lr[0]);
    const float invT   = 1.f / decode_scalar(temp_p);

    float lo[16];
    float mx = -INFINITY;
#pragma unroll
    for (int c = 0; c < 16; c++) {
        float cum = excl + p[c];
        float l = (av[c] - lr_abs * (g[c] - 2.f * cum)) * invT;
        lo[c] = l;
        mx = fmaxf(mx, l);
    }
#pragma unroll
    for (int o = 16; o > 0; o >>= 1) mx = fmaxf(mx, __shfl_xor_sync(0xffffffffu, mx, o));

    float s = 0.f;
#pragma unroll
    for (int c = 0; c < 16; c++) { lo[c] = __expf(lo[c] - mx); s += lo[c]; }
#pragma unroll
    for (int o = 16; o > 0; o >>= 1) s += __shfl_xor_sync(0xffffffffu, s, o);
    const float invS = 1.f / s;

    U16 oa;
#pragma unroll
    for (int c = 0; c < 16; c++) {
        float v = lo[c] * invS;
        oa.h[c] = __float2half(v);
        lo[c] = v;
    }
    *(uint4*)(g_a16 + base)     = oa.u4[0];
    *(uint4*)(g_a16 + base + 8) = oa.u4[1];

    if (last) {
        float* ar = a_out + base;
#pragma unroll
        for (int q = 0; q < 4; q++)
            *(float4*)(ar + q * 4) = make_float4(lo[q * 4 + 0], lo[q * 4 + 1],
                                                 lo[q * 4 + 2], lo[q * 4 + 3]);
    }
}

// ---------------------------------------------------------------------------
// y[b,k] = sum_i x[b,i] * a[b,i,k]; 16 i-chunks per batch + atomicAdd.
// (verbatim R8 — measured-safe high-parallelism form)
// ---------------------------------------------------------------------------
__global__ void init_y_kernel(float* __restrict__ y)
{
    y[blockIdx.x * 1024 + threadIdx.x] = 0.f;
}

__global__ void __launch_bounds__(512) y_kernel(
    const float* __restrict__ x, const float* __restrict__ a, float* __restrict__ y)
{
    int b  = blockIdx.x;
    int ch = blockIdx.y;
    int k  = threadIdx.x;
    __shared__ float xs[32];
    if (k < 32) xs[k] = x[b * NN + ch * 32 + k];
    __syncthreads();
    const float* ab = a + (size_t)b * NN * NN + (size_t)ch * 32 * NN;
    float a0 = 0.f, a1 = 0.f, a2 = 0.f, a3 = 0.f;
#pragma unroll
    for (int i = 0; i < 32; i += 4) {
        a0 = fmaf(xs[i + 0], ab[(size_t)(i + 0) * NN + k], a0);
        a1 = fmaf(xs[i + 1], ab[(size_t)(i + 1) * NN + k], a1);
        a2 = fmaf(xs[i + 2], ab[(size_t)(i + 2) * NN + k], a2);
        a3 = fmaf(xs[i + 3], ab[(size_t)(i + 3) * NN + k], a3);
    }
    atomicAdd(&y[b * NN + k], (a0 + a1) + (a2 + a3));
}

// ---------------------------------------------------------------------------
extern "C" void kernel_launch(void* const* d_in, const int* in_sizes, int n_in,
                              void* d_out, int out_size)
{
    const float* x   = (const float*)d_in[0];
    const float* w1  = (const float*)d_in[1];
    const float* b1  = (const float*)d_in[2];
    const float* w2  = (const float*)d_in[3];
    // d_in[4] = b2 (cancels in c - c^T), d_in[6] = steps (fixed at 8)
    const float* lr  = (const float*)d_in[5];
    const int* temp_p = (const int*)d_in[7];

    float* y = (float*)d_out;              // (32,1,512)
    float* a = (float*)d_out + NB * NN;    // (32,512,512), written on last step

    cudaFuncSetAttribute(gemm_mma_kernel, cudaFuncAttributeMaxDynamicSharedMemorySize, GEMM_SMEM);

    cstep0_kernel<<<dim3(NN / 8, NB), 256>>>(x, w1, b1, w2, lr, temp_p);

    for (int s = 0; s < 7; s++) {
        gemm_mma_kernel<<<dim3(4, 4, NB), 128, GEMM_SMEM>>>();
        epi_fuse_kernel<<<NB * NN / 8, 256>>>(a, lr, temp_p, (s == 6) ? 1 : 0);
    }

    init_y_kernel<<<NB * NN / 1024, 1024>>>(y);
    y_kernel<<<dim3(NB, 16), 512>>>(x, a, y);
}